// round 7
// baseline (speedup 1.0000x reference)
#include <cuda_runtime.h>
#include <cuda_bf16.h>

// Problem constants (fixed by the dataset)
#define T_LEN 262144
#define I_DIM 6
#define H_DIM 50      // real hidden size
#define HP    56      // padded hidden size (multiple of 8; dummy units identically 0)
#define GP    224     // 4*HP = threads per scan CTA (7 warps)

// Chunked-scan parameters: one chunk per resident CTA (3 CTAs/SM x 148 SMs)
#define C_CHUNKS 444
#define S_CHUNK  ((T_LEN + C_CHUNKS - 1) / C_CHUNKS)   // 591 owned steps
#define WARMUP   64                                    // contraction burn-in

__device__ float g_hs[T_LEN * H_DIM];   // 52 MB; h_t history for the output pass

typedef unsigned long long ull;

// ---------------- packed f32x2 / MUFU helpers ----------------
__device__ __forceinline__ ull pk2(float lo, float hi) {
    ull r; asm("mov.b64 %0, {%1, %2};" : "=l"(r) : "f"(lo), "f"(hi)); return r;
}
__device__ __forceinline__ ull fma2(ull a, ull b, ull c) {
    ull d; asm("fma.rn.f32x2 %0, %1, %2, %3;" : "=l"(d) : "l"(a), "l"(b), "l"(c)); return d;
}
__device__ __forceinline__ ull add2(ull a, ull b) {
    ull d; asm("add.rn.f32x2 %0, %1, %2;" : "=l"(d) : "l"(a), "l"(b)); return d;
}
__device__ __forceinline__ float2 upk(ull v) {
    float2 f; asm("mov.b64 {%0, %1}, %2;" : "=f"(f.x), "=f"(f.y) : "l"(v)); return f;
}
__device__ __forceinline__ float tanhap(float x) {
    float y; asm("tanh.approx.f32 %0, %1;" : "=f"(y) : "f"(x)); return y;
}

// ---------------- Kernel 1: chunked LSTM scan ----------------
// CTA = one chunk. Thread p: j = p/4 (hidden unit 0..55), k = p%4 (gate i,f,g,o).
// Chunk c owns steps [c*S, min((c+1)*S,T)); starts WARMUP steps earlier from
// zero state (exact for c==0; converged to the true state by contraction).
// NOTE: the 2-step unrolled loop may execute ONE phantom step at step==own_end
// when (own_end-start) is odd; all global writes are guarded by step < own_end.
__global__ void __launch_bounds__(GP, 3)
lstm_scan_chunks(const float* __restrict__ X,
                 const float* __restrict__ Wih,
                 const float* __restrict__ Whh,
                 const float* __restrict__ bih,
                 const float* __restrict__ bhh) {
    __shared__ __align__(16) float h_sh[2][HP];

    const int chunk = blockIdx.x;
    const int own_start = chunk * S_CHUNK;
    const int own_end   = min(own_start + S_CHUNK, T_LEN);
    const int start     = max(0, own_start - WARMUP);
    if (own_start >= T_LEN) return;

    const int tid  = threadIdx.x;
    const int j    = tid >> 2;
    const int k    = tid & 3;
    const int lane = tid & 31;
    const int qb   = lane & ~3;
    const bool realj = (j < H_DIM);

    // Register-resident weights (zeros for pad rows / pad columns)
    ull whv[HP / 2];          // W_hh row, 28 packed pairs
    ull wxv[I_DIM / 2];       // W_ih row, 3 packed pairs
    float bias = 0.0f;
#pragma unroll
    for (int m = 0; m < HP / 2; m++) whv[m] = 0ull;
#pragma unroll
    for (int m = 0; m < I_DIM / 2; m++) wxv[m] = 0ull;
    if (realj) {
        const int r = k * H_DIM + j;
        const float* wr = Whh + r * H_DIM;
#pragma unroll
        for (int m = 0; m < H_DIM / 2; m++)
            whv[m] = pk2(__ldg(&wr[2 * m]), __ldg(&wr[2 * m + 1]));
        const float* wx = Wih + r * I_DIM;
#pragma unroll
        for (int m = 0; m < I_DIM / 2; m++)
            wxv[m] = pk2(__ldg(&wx[2 * m]), __ldg(&wx[2 * m + 1]));
        bias = __ldg(&bih[r]) + __ldg(&bhh[r]);
    }

    // Branch-free activation: k==2 (g) -> tanh(x); else sigmoid = 0.5*tanh(0.5x)+0.5
    const float Sc = (k == 2) ? 1.0f : 0.5f;
    const float Aa = (k == 2) ? 1.0f : 0.5f;
    const float Bb = (k == 2) ? 0.0f : 0.5f;

    float c = 0.0f;
    if (tid < HP) { h_sh[0][tid] = 0.0f; h_sh[1][tid] = 0.0f; }

    // depth-2 x prefetch: xp{0,1} hold x[t], x[t+1] packed as 3 f32x2 each
    ull xp0[3], xp1[3];
    {
        const float2* x0 = (const float2*)(X + (size_t)start * I_DIM);
#pragma unroll
        for (int m = 0; m < 3; m++) { float2 v = __ldg(&x0[m]); xp0[m] = pk2(v.x, v.y); }
        const float2* x1 = (const float2*)(X + (size_t)(start + 1) * I_DIM);
#pragma unroll
        for (int m = 0; m < 3; m++) { float2 v = __ldg(&x1[m]); xp1[m] = pk2(v.x, v.y); }
    }

    __syncthreads();

    for (int t = start; t < own_end; t += 2) {
#pragma unroll
        for (int p = 0; p < 2; p++) {
            const int step = t + p;
            ull* xc = p ? xp1 : xp0;

            // accumulate: bias + x-part (3 fma2) + h-part (28 fma2, 4 chains)
            ull a0 = fma2(wxv[0], xc[0], pk2(bias, 0.0f));
            ull a1 = fma2(wxv[1], xc[1], 0ull);
            ull a2 = fma2(wxv[2], xc[2], 0ull);
            ull a3 = 0ull;

            // prefetch x for step+2 into this parity's regs (off critical path)
            if (step + 2 < own_end) {
                const float2* xn = (const float2*)(X + (size_t)(step + 2) * I_DIM);
#pragma unroll
                for (int m = 0; m < 3; m++) { float2 v = __ldg(&xn[m]); xc[m] = pk2(v.x, v.y); }
            }

            const ulonglong2* h8 = (const ulonglong2*)h_sh[step & 1];
#pragma unroll
            for (int q = 0; q < HP / 4; q += 2) {
                ulonglong2 v0 = h8[q];
                ulonglong2 v1 = h8[q + 1];
                a0 = fma2(whv[2 * q],     v0.x, a0);
                a1 = fma2(whv[2 * q + 1], v0.y, a1);
                a2 = fma2(whv[2 * q + 2], v1.x, a2);
                a3 = fma2(whv[2 * q + 3], v1.y, a3);
            }
            float2 s = upk(add2(add2(a0, a1), add2(a2, a3)));
            float pre = s.x + s.y;

            // gate activation
            float val = fmaf(Aa, tanhap(Sc * pre), Bb);

            // gather quad gates
            float vi = __shfl_sync(0xffffffffu, val, qb);
            float vf = __shfl_sync(0xffffffffu, val, qb + 1);
            float vg = __shfl_sync(0xffffffffu, val, qb + 2);
            float vo = __shfl_sync(0xffffffffu, val, qb + 3);

            // carry + hidden update (replicated across quad; pad units stay 0)
            c = fmaf(vf, c, vi * vg);
            float hn = vo * tanhap(c);

            if (k == 0) {
                h_sh[(step + 1) & 1][j] = hn;                       // next step's input
                // guarded: phantom step (step==own_end) must not write history
                if (realj && step >= own_start && step < own_end)
                    g_hs[(size_t)step * H_DIM + j] = hn;            // owned history
            }
            __syncthreads();
        }
    }
}

// ---------------- Kernel 2: output head (1 timestep/thread — measured fastest) ----------------
__global__ void out_kernel(const float* __restrict__ Wlin,
                           const float* __restrict__ blin,
                           float* __restrict__ out) {
    int t = blockIdx.x * blockDim.x + threadIdx.x;
    if (t >= T_LEN) return;
    const float2* h2 = (const float2*)(g_hs + (size_t)t * H_DIM);
    float acc = __ldg(&blin[0]);
#pragma unroll
    for (int m = 0; m < H_DIM / 2; m++) {
        float2 hv = h2[m];
        float2 wv = __ldg(&((const float2*)Wlin)[m]);
        acc = fmaf(hv.x, wv.x, fmaf(hv.y, wv.y, acc));
    }
    out[t] = 1.0f / (1.0f + __expf(-acc));
}

// ---------------- launch ----------------
extern "C" void kernel_launch(void* const* d_in, const int* in_sizes, int n_in,
                              void* d_out, int out_size) {
    const float* X    = (const float*)d_in[0];
    const float* Wih  = (const float*)d_in[1];
    const float* Whh  = (const float*)d_in[2];
    const float* bih  = (const float*)d_in[3];
    const float* bhh  = (const float*)d_in[4];
    const float* Wlin = (const float*)d_in[5];
    const float* blin = (const float*)d_in[6];
    float* out = (float*)d_out;

    lstm_scan_chunks<<<C_CHUNKS, GP>>>(X, Wih, Whh, bih, bhh);
    out_kernel<<<(T_LEN + 255) / 256, 256>>>(Wlin, blin, out);
}

// round 8
// speedup vs baseline: 1.2023x; 1.2023x over previous
#include <cuda_runtime.h>
#include <cuda_bf16.h>

// Problem constants (fixed by the dataset)
#define T_LEN 262144
#define I_DIM 6
#define H_DIM 50      // real hidden size
#define HP    56      // padded ROW count/4 (quad granularity); columns are exact (50)
#define GP    224     // 4*HP = threads per scan CTA (7 warps)

// Chunked-scan parameters: one chunk per resident CTA (2 CTAs/SM x 148 SMs)
#define C_CHUNKS 296
#define S_CHUNK  ((T_LEN + C_CHUNKS - 1) / C_CHUNKS)   // 886 owned steps
#define WARMUP   40                                    // contraction burn-in

__device__ float g_hs[T_LEN * H_DIM];   // 52 MB; h_t history (L2-resident for epilogue)

typedef unsigned long long ull;

// ---------------- packed f32x2 / MUFU helpers ----------------
__device__ __forceinline__ ull pk2(float lo, float hi) {
    ull r; asm("mov.b64 %0, {%1, %2};" : "=l"(r) : "f"(lo), "f"(hi)); return r;
}
__device__ __forceinline__ ull fma2(ull a, ull b, ull c) {
    ull d; asm("fma.rn.f32x2 %0, %1, %2, %3;" : "=l"(d) : "l"(a), "l"(b), "l"(c)); return d;
}
__device__ __forceinline__ ull add2(ull a, ull b) {
    ull d; asm("add.rn.f32x2 %0, %1, %2;" : "=l"(d) : "l"(a), "l"(b)); return d;
}
__device__ __forceinline__ float2 upk(ull v) {
    float2 f; asm("mov.b64 {%0, %1}, %2;" : "=f"(f.x), "=f"(f.y) : "l"(v)); return f;
}
__device__ __forceinline__ float tanhap(float x) {
    float y; asm("tanh.approx.f32 %0, %1;" : "=f"(y) : "f"(x)); return y;
}

// ---------------- Kernel: chunked LSTM scan + fused output head ----------------
// CTA = one chunk. Thread p: j = p/4 (hidden unit 0..55), k = p%4 (gate i,f,g,o).
// Chunk c owns steps [c*S, min((c+1)*S,T)); starts WARMUP steps earlier from
// zero state (exact for c==0; converged to the true state by contraction).
// Gate-input scale (0.5 for sigmoid gates) is FOLDED into W/bias at load time,
// so the per-step activation is just tanh.approx + one FFMA.
__global__ void __launch_bounds__(GP, 2)
lstm_scan_chunks(const float* __restrict__ X,
                 const float* __restrict__ Wih,
                 const float* __restrict__ Whh,
                 const float* __restrict__ bih,
                 const float* __restrict__ bhh,
                 const float* __restrict__ Wlin,
                 const float* __restrict__ blin,
                 float* __restrict__ out) {
    __shared__ __align__(16) float h_sh[2][HP];

    const int chunk = blockIdx.x;
    const int own_start = chunk * S_CHUNK;
    const int own_end   = min(own_start + S_CHUNK, T_LEN);
    const int start     = max(0, own_start - WARMUP);
    if (own_start >= T_LEN) return;

    const int tid  = threadIdx.x;
    const int j    = tid >> 2;
    const int k    = tid & 3;
    const int lane = tid & 31;
    const int qb   = lane & ~3;
    const bool realj = (j < H_DIM);

    // Pre-scaled register-resident weights (zeros for pad rows).
    // Scale 0.5 folded for sigmoid gates (k != 2): sigmoid(x) = 0.5*tanh(0.5x)+0.5.
    const float wscale = (k == 2) ? 1.0f : 0.5f;
    ull whv[H_DIM / 2];       // 25 packed pairs (columns exact, no padding)
    ull wxv[I_DIM / 2];       // 3 packed pairs
    ull biasPair = 0ull;      // pk2(scaled bias, 0) — fma2 addend for chain a0
#pragma unroll
    for (int m = 0; m < H_DIM / 2; m++) whv[m] = 0ull;
#pragma unroll
    for (int m = 0; m < I_DIM / 2; m++) wxv[m] = 0ull;
    if (realj) {
        const int r = k * H_DIM + j;
        const float* wr = Whh + r * H_DIM;
#pragma unroll
        for (int m = 0; m < H_DIM / 2; m++)
            whv[m] = pk2(wscale * __ldg(&wr[2 * m]), wscale * __ldg(&wr[2 * m + 1]));
        const float* wx = Wih + r * I_DIM;
#pragma unroll
        for (int m = 0; m < I_DIM / 2; m++)
            wxv[m] = pk2(wscale * __ldg(&wx[2 * m]), wscale * __ldg(&wx[2 * m + 1]));
        biasPair = pk2(wscale * (__ldg(&bih[r]) + __ldg(&bhh[r])), 0.0f);
    }

    // Activation affine: k==2 -> tanh(x); else 0.5*tanh(scaled pre)+0.5
    const float Aa = (k == 2) ? 1.0f : 0.5f;
    const float Bb = (k == 2) ? 0.0f : 0.5f;

    float c = 0.0f;
    if (tid < HP) { h_sh[0][tid] = 0.0f; h_sh[1][tid] = 0.0f; }

    // depth-2 x prefetch: xp{0,1} hold x[t], x[t+1] packed as 3 f32x2 each
    ull xp0[3], xp1[3];
    {
        const float2* x0 = (const float2*)(X + (size_t)start * I_DIM);
#pragma unroll
        for (int m = 0; m < 3; m++) { float2 v = __ldg(&x0[m]); xp0[m] = pk2(v.x, v.y); }
        const float2* x1 = (const float2*)(X + (size_t)(start + 1) * I_DIM);
#pragma unroll
        for (int m = 0; m < 3; m++) { float2 v = __ldg(&x1[m]); xp1[m] = pk2(v.x, v.y); }
    }

    __syncthreads();

    for (int t = start; t < own_end; t += 2) {
#pragma unroll
        for (int p = 0; p < 2; p++) {
            const int step = t + p;
            ull* xc = p ? xp1 : xp0;

            // accumulate: bias + x-part (3 fma2) then h-part (25 fma2, 4 chains)
            ull a0 = fma2(wxv[0], xc[0], biasPair);
            ull a1 = fma2(wxv[1], xc[1], 0ull);
            ull a2 = fma2(wxv[2], xc[2], 0ull);
            ull a3 = 0ull;

            // prefetch x for step+2 into this parity's regs (off critical path)
            if (step + 2 < own_end) {
                const float2* xn = (const float2*)(X + (size_t)(step + 2) * I_DIM);
#pragma unroll
                for (int m = 0; m < 3; m++) { float2 v = __ldg(&xn[m]); xc[m] = pk2(v.x, v.y); }
            }

            const float* hb = h_sh[step & 1];
            const ulonglong2* h8 = (const ulonglong2*)hb;
            // 24 pairs via 12 LDS.128, round-robin into 4 chains
#pragma unroll
            for (int q = 0; q < 12; q += 2) {
                ulonglong2 v0 = h8[q];
                ulonglong2 v1 = h8[q + 1];
                a0 = fma2(whv[2 * q],     v0.x, a0);
                a1 = fma2(whv[2 * q + 1], v0.y, a1);
                a2 = fma2(whv[2 * q + 2], v1.x, a2);
                a3 = fma2(whv[2 * q + 3], v1.y, a3);
            }
            // final pair (cols 48,49) via LDS.64
            a3 = fma2(whv[24], *(const ull*)(hb + 48), a3);

            float2 s = upk(add2(add2(a0, a1), add2(a2, a3)));
            float pre = s.x + s.y;

            // gate activation (scale pre-folded into weights)
            float val = fmaf(Aa, tanhap(pre), Bb);

            // gather quad gates
            float vi = __shfl_sync(0xffffffffu, val, qb);
            float vf = __shfl_sync(0xffffffffu, val, qb + 1);
            float vg = __shfl_sync(0xffffffffu, val, qb + 2);
            float vo = __shfl_sync(0xffffffffu, val, qb + 3);

            // carry + hidden update (replicated across quad; pad units stay 0)
            c = fmaf(vf, c, vi * vg);
            float hn = vo * tanhap(c);

            if (k == 0) {
                h_sh[(step + 1) & 1][j] = hn;                       // next step's input
                if (realj && step >= own_start && step < own_end)
                    g_hs[(size_t)step * H_DIM + j] = hn;            // owned history
            }
            __syncthreads();
        }
    }

    // ---- fused output head over this chunk's owned steps (g_hs is L2-hot) ----
    __syncthreads();   // make k==0 threads' global g_hs writes visible CTA-wide
    const float b0 = __ldg(&blin[0]);
    for (int t = own_start + tid; t < own_end; t += GP) {
        const float2* h2 = (const float2*)(g_hs + (size_t)t * H_DIM);
        float acc = b0;
#pragma unroll
        for (int m = 0; m < H_DIM / 2; m++) {
            float2 hv = h2[m];
            float2 wv = __ldg(&((const float2*)Wlin)[m]);
            acc = fmaf(hv.x, wv.x, fmaf(hv.y, wv.y, acc));
        }
        out[t] = 1.0f / (1.0f + __expf(-acc));
    }
}

// ---------------- launch ----------------
extern "C" void kernel_launch(void* const* d_in, const int* in_sizes, int n_in,
                              void* d_out, int out_size) {
    const float* X    = (const float*)d_in[0];
    const float* Wih  = (const float*)d_in[1];
    const float* Whh  = (const float*)d_in[2];
    const float* bih  = (const float*)d_in[3];
    const float* bhh  = (const float*)d_in[4];
    const float* Wlin = (const float*)d_in[5];
    const float* blin = (const float*)d_in[6];
    float* out = (float*)d_out;

    lstm_scan_chunks<<<C_CHUNKS, GP>>>(X, Wih, Whh, bih, bhh, Wlin, blin, out);
}

// round 9
// speedup vs baseline: 1.5754x; 1.3103x over previous
#include <cuda_runtime.h>
#include <cuda_bf16.h>

// Problem constants (fixed by the dataset)
#define T_LEN 262144
#define I_DIM 6
#define H_DIM 50      // real hidden size
#define HP2   64      // padded hidden units (pad units identically 0)
#define GP    128     // 2*HP2 threads per scan CTA (4 warps): thread=(unit, gate-pair)

// Chunked-scan parameters: one chunk per resident CTA (2 CTAs/SM x 148 SMs)
#define C_CHUNKS 296
#define S_CHUNK  ((T_LEN + C_CHUNKS - 1) / C_CHUNKS)   // 886 owned steps
#define WARMUP   40                                    // contraction burn-in (926 total: even)

__device__ float g_hs[T_LEN * H_DIM];   // 52 MB; h_t history (L2-hot for fused epilogue)

typedef unsigned long long ull;

// ---------------- packed f32x2 / MUFU helpers ----------------
__device__ __forceinline__ ull pk2(float lo, float hi) {
    ull r; asm("mov.b64 %0, {%1, %2};" : "=l"(r) : "f"(lo), "f"(hi)); return r;
}
__device__ __forceinline__ ull fma2(ull a, ull b, ull c) {
    ull d; asm("fma.rn.f32x2 %0, %1, %2, %3;" : "=l"(d) : "l"(a), "l"(b), "l"(c)); return d;
}
__device__ __forceinline__ ull add2(ull a, ull b) {
    ull d; asm("add.rn.f32x2 %0, %1, %2;" : "=l"(d) : "l"(a), "l"(b)); return d;
}
__device__ __forceinline__ float2 upk(ull v) {
    float2 f; asm("mov.b64 {%0, %1}, %2;" : "=f"(f.x), "=f"(f.y) : "l"(v)); return f;
}
__device__ __forceinline__ float tanhap(float x) {
    float y; asm("tanh.approx.f32 %0, %1;" : "=f"(y) : "f"(x)); return y;
}

// ---------------- Kernel: chunked LSTM scan + fused output head ----------------
// Thread p: j = p/2 (hidden unit 0..63), k2 = p%2.
//   k2==0 -> gate rows i (0H+j) and f (1H+j)
//   k2==1 -> gate rows g (2H+j) and o (3H+j)
// Each thread loads the h vector ONCE per step and feeds TWO gate rows
// (halves the LDS wavefront pressure that bound R7). Gate-input scale (0.5 for
// sigmoid gates) folded into W/bias. One shfl_xor pair exchanges (g,o) into the
// (i,f) thread, which owns c and writes h.
__global__ void __launch_bounds__(GP, 2)
lstm_scan_chunks(const float* __restrict__ X,
                 const float* __restrict__ Wih,
                 const float* __restrict__ Whh,
                 const float* __restrict__ bih,
                 const float* __restrict__ bhh,
                 const float* __restrict__ Wlin,
                 const float* __restrict__ blin,
                 float* __restrict__ out) {
    __shared__ __align__(16) float h_sh[2][HP2];

    const int chunk = blockIdx.x;
    const int own_start = chunk * S_CHUNK;
    const int own_end   = min(own_start + S_CHUNK, T_LEN);
    const int start     = max(0, own_start - WARMUP);
    if (own_start >= T_LEN) return;

    const int tid = threadIdx.x;
    const int j   = tid >> 1;
    const int k2  = tid & 1;
    const bool realj = (j < H_DIM);

    // Row A: k2==0 -> i (sigmoid), k2==1 -> g (tanh)
    // Row B: k2==0 -> f (sigmoid), k2==1 -> o (sigmoid)
    const int   rA = (k2 == 0) ? (0 * H_DIM + j) : (2 * H_DIM + j);
    const int   rB = (k2 == 0) ? (1 * H_DIM + j) : (3 * H_DIM + j);
    const float sA = (k2 == 0) ? 0.5f : 1.0f;   // folded input scale
    const float sB = 0.5f;
    const float AaA = (k2 == 0) ? 0.5f : 1.0f;  // affine after tanh
    const float BbA = (k2 == 0) ? 0.5f : 0.0f;
    // Row B is always sigmoid: 0.5*tanh+0.5

    // Register-resident pre-scaled weights (zeros for pad units)
    ull whA[H_DIM / 2], whB[H_DIM / 2];   // 25 + 25 packed pairs
    ull wxA[I_DIM / 2], wxB[I_DIM / 2];   // 3 + 3 packed pairs
    ull biasA = 0ull, biasB = 0ull;
#pragma unroll
    for (int m = 0; m < H_DIM / 2; m++) { whA[m] = 0ull; whB[m] = 0ull; }
#pragma unroll
    for (int m = 0; m < I_DIM / 2; m++) { wxA[m] = 0ull; wxB[m] = 0ull; }
    if (realj) {
        const float* wrA = Whh + rA * H_DIM;
        const float* wrB = Whh + rB * H_DIM;
#pragma unroll
        for (int m = 0; m < H_DIM / 2; m++) {
            whA[m] = pk2(sA * __ldg(&wrA[2 * m]), sA * __ldg(&wrA[2 * m + 1]));
            whB[m] = pk2(sB * __ldg(&wrB[2 * m]), sB * __ldg(&wrB[2 * m + 1]));
        }
        const float* wxa = Wih + rA * I_DIM;
        const float* wxb = Wih + rB * I_DIM;
#pragma unroll
        for (int m = 0; m < I_DIM / 2; m++) {
            wxA[m] = pk2(sA * __ldg(&wxa[2 * m]), sA * __ldg(&wxa[2 * m + 1]));
            wxB[m] = pk2(sB * __ldg(&wxb[2 * m]), sB * __ldg(&wxb[2 * m + 1]));
        }
        biasA = pk2(sA * (__ldg(&bih[rA]) + __ldg(&bhh[rA])), 0.0f);
        biasB = pk2(sB * (__ldg(&bih[rB]) + __ldg(&bhh[rB])), 0.0f);
    }

    float c = 0.0f;
    if (tid < HP2) { h_sh[0][tid] = 0.0f; h_sh[1][tid] = 0.0f; }

    // depth-2 x prefetch: xp{0,1} hold x[t], x[t+1] packed as 3 f32x2 each
    ull xp0[3], xp1[3];
    {
        const float2* x0 = (const float2*)(X + (size_t)start * I_DIM);
#pragma unroll
        for (int m = 0; m < 3; m++) { float2 v = __ldg(&x0[m]); xp0[m] = pk2(v.x, v.y); }
        const float2* x1 = (const float2*)(X + (size_t)(start + 1) * I_DIM);
#pragma unroll
        for (int m = 0; m < 3; m++) { float2 v = __ldg(&x1[m]); xp1[m] = pk2(v.x, v.y); }
    }

    __syncthreads();

    for (int t = start; t < own_end; t += 2) {
#pragma unroll
        for (int p = 0; p < 2; p++) {
            const int step = t + p;
            ull* xc = p ? xp1 : xp0;

            // x-part + bias (3 fma2 per row), 2 chains per row
            ull aA0 = fma2(wxA[0], xc[0], biasA);
            ull aA1 = fma2(wxA[1], xc[1], 0ull);
            ull aB0 = fma2(wxB[0], xc[0], biasB);
            ull aB1 = fma2(wxB[1], xc[1], 0ull);
            aA0 = fma2(wxA[2], xc[2], aA0);
            aB0 = fma2(wxB[2], xc[2], aB0);

            // prefetch x for step+2 (off critical path)
            if (step + 2 < own_end) {
                const float2* xn = (const float2*)(X + (size_t)(step + 2) * I_DIM);
#pragma unroll
                for (int m = 0; m < 3; m++) { float2 v = __ldg(&xn[m]); xc[m] = pk2(v.x, v.y); }
            }

            const float* hb = h_sh[step & 1];
            const ulonglong2* h8 = (const ulonglong2*)hb;
            // h loaded ONCE (12 LDS.128 + 1 LDS.64), feeds BOTH gate rows
#pragma unroll
            for (int q = 0; q < 12; q++) {
                ulonglong2 v = h8[q];
                aA0 = fma2(whA[2 * q],     v.x, aA0);
                aA1 = fma2(whA[2 * q + 1], v.y, aA1);
                aB0 = fma2(whB[2 * q],     v.x, aB0);
                aB1 = fma2(whB[2 * q + 1], v.y, aB1);
            }
            {
                ull vt = *(const ull*)(hb + 48);      // cols 48,49
                aA0 = fma2(whA[24], vt, aA0);
                aB0 = fma2(whB[24], vt, aB0);
            }
            float2 fA = upk(add2(aA0, aA1));
            float2 fB = upk(add2(aB0, aB1));
            float preA = fA.x + fA.y;
            float preB = fB.x + fB.y;

            // activations: rowA = i or g; rowB = f or o
            float valA = fmaf(AaA, tanhap(preA), BbA);
            float valB = fmaf(0.5f, tanhap(preB), 0.5f);

            // exchange with pair thread: even gets (g,o); odd gets (i,f) [unused]
            float vg = __shfl_xor_sync(0xffffffffu, valA, 1);
            float vo = __shfl_xor_sync(0xffffffffu, valB, 1);

            // even thread: valA=i, valB=f, vg=g, vo=o
            c = fmaf(valB, c, valA * vg);
            float hn = vo * tanhap(c);

            if (k2 == 0) {
                h_sh[(step + 1) & 1][j] = hn;                       // next step's input
                if (realj && step >= own_start && step < own_end)
                    g_hs[(size_t)step * H_DIM + j] = hn;            // owned history
            }
            __syncthreads();
        }
    }

    // ---- fused output head over this chunk's owned steps (g_hs is L2-hot) ----
    __syncthreads();
    const float b0 = __ldg(&blin[0]);
    for (int t = own_start + tid; t < own_end; t += GP) {
        const float2* h2 = (const float2*)(g_hs + (size_t)t * H_DIM);
        float acc = b0;
#pragma unroll
        for (int m = 0; m < H_DIM / 2; m++) {
            float2 hv = h2[m];
            float2 wv = __ldg(&((const float2*)Wlin)[m]);
            acc = fmaf(hv.x, wv.x, fmaf(hv.y, wv.y, acc));
        }
        out[t] = 1.0f / (1.0f + __expf(-acc));
    }
}

// ---------------- launch ----------------
extern "C" void kernel_launch(void* const* d_in, const int* in_sizes, int n_in,
                              void* d_out, int out_size) {
    const float* X    = (const float*)d_in[0];
    const float* Wih  = (const float*)d_in[1];
    const float* Whh  = (const float*)d_in[2];
    const float* bih  = (const float*)d_in[3];
    const float* bhh  = (const float*)d_in[4];
    const float* Wlin = (const float*)d_in[5];
    const float* blin = (const float*)d_in[6];
    float* out = (float*)d_out;

    lstm_scan_chunks<<<C_CHUNKS, GP>>>(X, Wih, Whh, bih, bhh, Wlin, blin, out);
}